// round 4
// baseline (speedup 1.0000x reference)
#include <cuda_runtime.h>
#include <cuda_fp16.h>
#include <math.h>
#include <stdint.h>

// ---------------- problem dims ----------------
#define T_TOK 2048
#define H_DIM 1024
#define F_DIM 4096
#define E_NUM 8
#define CAP   2048

// ---------------- GEMM tiling ----------------
#define BM 256
#define BN 128
#define BK 32
#define AS 40      // As row stride (halves), 80B rows: conflict-free ldmatrix
#define BS 136     // Bs row stride (halves), 272B rows: conflict-free ldmatrix.trans

#define ABYTES (BM * AS * 2)          // 20480
#define BBYTES (BK * BS * 2)          // 8704
#define SMB    (2 * ABYTES)           // Bs buffers start
#define SMEM_TOTAL (2 * ABYTES + 2 * BBYTES)   // 58368

// ---------------- device scratch ----------------
__device__ int    d_cnt[E_NUM];
__device__ int    d_tok[E_NUM * CAP];
__device__ float  d_wt [E_NUM * CAP];
__device__ __half d_x16[T_TOK * H_DIM];
__device__ __half d_hbuf[(size_t)E_NUM * CAP * F_DIM];   // h in f16

// ---------------- helpers ----------------
__device__ __forceinline__ uint32_t smem_u32(const void* p) {
    uint32_t a;
    asm("{ .reg .u64 t; cvta.to.shared.u64 t, %1; cvt.u32.u64 %0, t; }" : "=r"(a) : "l"(p));
    return a;
}
__device__ __forceinline__ void ldsm4(uint32_t r[4], uint32_t addr) {
    asm volatile("ldmatrix.sync.aligned.m8n8.x4.shared.b16 {%0,%1,%2,%3}, [%4];"
                 : "=r"(r[0]), "=r"(r[1]), "=r"(r[2]), "=r"(r[3]) : "r"(addr));
}
__device__ __forceinline__ void ldsm4t(uint32_t r[4], uint32_t addr) {
    asm volatile("ldmatrix.sync.aligned.m8n8.x4.trans.shared.b16 {%0,%1,%2,%3}, [%4];"
                 : "=r"(r[0]), "=r"(r[1]), "=r"(r[2]), "=r"(r[3]) : "r"(addr));
}
__device__ __forceinline__ void mma16816(float c[4], const uint32_t a[4],
                                         uint32_t b0, uint32_t b1) {
    asm volatile(
        "mma.sync.aligned.m16n8k16.row.col.f32.f16.f16.f32 "
        "{%0,%1,%2,%3}, {%4,%5,%6,%7}, {%8,%9}, {%0,%1,%2,%3};\n"
        : "+f"(c[0]), "+f"(c[1]), "+f"(c[2]), "+f"(c[3])
        : "r"(a[0]), "r"(a[1]), "r"(a[2]), "r"(a[3]), "r"(b0), "r"(b1));
}
__device__ __forceinline__ void cpa16(uint32_t dst, const void* src) {
    asm volatile("cp.async.ca.shared.global [%0], [%1], 16;" :: "r"(dst), "l"(src));
}
#define CP_COMMIT() asm volatile("cp.async.commit_group;" ::: "memory")
#define CP_WAIT0()  asm volatile("cp.async.wait_group 0;" ::: "memory")
__device__ __forceinline__ uint32_t pk(float a, float b) {
    half2 h = __floats2half2_rn(a, b);
    return *(uint32_t*)&h;
}

// ---------------- kernel 0: zero out + counters + convert x -> f16 ----------------
__global__ void moe_zero_kernel(const float4* __restrict__ x, float4* __restrict__ out) {
    int i = blockIdx.x * blockDim.x + threadIdx.x;
    if (i < E_NUM) d_cnt[i] = 0;
    int stride = gridDim.x * blockDim.x;
    for (int j = i; j < T_TOK * H_DIM / 4; j += stride) {
        out[j] = make_float4(0.f, 0.f, 0.f, 0.f);
        float4 v = x[j];
        uint2 u = make_uint2(pk(v.x, v.y), pk(v.z, v.w));
        *(uint2*)(d_x16 + (size_t)j * 4) = u;
    }
}

// ---------------- kernel 1: router (warp per token) ----------------
__global__ __launch_bounds__(256) void moe_router_kernel(
    const float* __restrict__ x, const float* __restrict__ gw, const float* __restrict__ gb)
{
    int t = blockIdx.x * 8 + (threadIdx.x >> 5);
    int lane = threadIdx.x & 31;
    if (t >= T_TOK) return;
    float s[E_NUM];
    #pragma unroll
    for (int e = 0; e < E_NUM; e++) s[e] = 0.f;
    #pragma unroll 4
    for (int j = 0; j < H_DIM / 32; j++) {
        float xv = x[(size_t)t * H_DIM + j * 32 + lane];
        const float4* g = (const float4*)(gw + (size_t)(j * 32 + lane) * E_NUM);
        float4 g0 = g[0], g1 = g[1];
        s[0] += xv * g0.x; s[1] += xv * g0.y; s[2] += xv * g0.z; s[3] += xv * g0.w;
        s[4] += xv * g1.x; s[5] += xv * g1.y; s[6] += xv * g1.z; s[7] += xv * g1.w;
    }
    #pragma unroll
    for (int e = 0; e < E_NUM; e++) {
        #pragma unroll
        for (int o = 16; o; o >>= 1) s[e] += __shfl_xor_sync(0xffffffffu, s[e], o);
    }
    if (lane == 0) {
        float lg[E_NUM];
        #pragma unroll
        for (int e = 0; e < E_NUM; e++) lg[e] = s[e] + gb[e];
        int i1 = 0; float l1 = lg[0];
        #pragma unroll
        for (int e = 1; e < E_NUM; e++) if (lg[e] > l1) { l1 = lg[e]; i1 = e; }
        int i2 = -1; float l2 = -1e30f;
        #pragma unroll
        for (int e = 0; e < E_NUM; e++) if (e != i1 && lg[e] > l2) { l2 = lg[e]; i2 = e; }
        float p1 = 1.0f / (1.0f + expf(l2 - l1));
        float p2 = 1.0f - p1;
        int q1 = atomicAdd(&d_cnt[i1], 1);
        d_tok[i1 * CAP + q1] = t;  d_wt[i1 * CAP + q1] = p1;
        int q2 = atomicAdd(&d_cnt[i2], 1);
        d_tok[i2 * CAP + q2] = t;  d_wt[i2 * CAP + q2] = p2;
    }
}

// ================= GEMM core (shared by both FFN kernels) =================
// CTA 256x128x32, 8 warps of 64x64, double-buffered: A via cp.async, B via
// register prefetch (f32 -> f16 packed STS.128).
struct GemmCore {
    uint32_t aB[2], bB[2];   // per-buffer ldmatrix base addresses
    float acc[4][8][4];
};

// ---------------- kernel 2: GEMM1  h = relu(X_gather @ W1[e] + b1) ----------------
__global__ __launch_bounds__(256, 1) void moe_ffn1_kernel(
    const float* __restrict__ w1, const float* __restrict__ b1)
{
    int e  = blockIdx.z;
    int M  = d_cnt[e];
    int m0 = blockIdx.y * BM;
    if (m0 >= M) return;
    int n0 = blockIdx.x * BN;

    extern __shared__ char smem[];
    uint32_t sb = smem_u32(smem);

    int tid = threadIdx.x, warp = tid >> 5, lane = tid & 31;
    int wm = warp >> 1, wn = warp & 1;           // 4x2 warps, 64x64 each
    int grp = lane >> 2, t4 = lane & 3;
    int lrow = lane & 15, lsel = lane >> 4;

    // A: one row per thread (gathered token), 4x 16B chunks along k
    int ar = tid;
    int gr = m0 + ar;
    int tokA = d_tok[e * CAP + ((gr < M) ? gr : 0)];
    const __half* arow = d_x16 + (size_t)tokA * H_DIM;
    uint32_t adst = sb + ar * 80;
    // B: thread -> (k-row kl, 16 cols at nq)
    int kl = tid >> 3, nq = (tid & 7) * 16;
    const float4* bsrc = (const float4*)(w1 + ((size_t)e * H_DIM + kl) * F_DIM + n0 + nq);
    const size_t bstep = (size_t)BK * F_DIM / 4;
    __half* bdst = (__half*)(smem + SMB) + kl * BS + nq;

    uint32_t aB[2], bB[2];
    #pragma unroll
    for (int b = 0; b < 2; b++) {
        aB[b] = sb + b * ABYTES + ((wm * 64 + lrow) * AS + lsel * 8) * 2;
        bB[b] = sb + SMB + b * BBYTES + (lrow * BS + wn * 64 + lsel * 8) * 2;
    }

    float acc[4][8][4];
    #pragma unroll
    for (int mi = 0; mi < 4; mi++)
        #pragma unroll
        for (int ni = 0; ni < 8; ni++)
            #pragma unroll
            for (int j = 0; j < 4; j++) acc[mi][ni][j] = 0.f;

    const int NIT = H_DIM / BK;   // 32
    // prologue: A(0) via cp.async, B(0) via LDG
    #pragma unroll
    for (int c = 0; c < 4; c++) cpa16(adst + c * 16, arow + c * 8);
    CP_COMMIT();
    float4 pb0 = bsrc[0], pb1 = bsrc[1], pb2 = bsrc[2], pb3 = bsrc[3];

    for (int it = 0; it < NIT; ++it) {
        int b = it & 1;
        // store B(it) packed
        {
            uint4 u0 = make_uint4(pk(pb0.x, pb0.y), pk(pb0.z, pb0.w),
                                  pk(pb1.x, pb1.y), pk(pb1.z, pb1.w));
            uint4 u1 = make_uint4(pk(pb2.x, pb2.y), pk(pb2.z, pb2.w),
                                  pk(pb3.x, pb3.y), pk(pb3.z, pb3.w));
            __half* bd = bdst + b * (BBYTES / 2);
            *(uint4*)bd = u0;
            *(uint4*)(bd + 8) = u1;
        }
        CP_WAIT0();
        __syncthreads();
        if (it + 1 < NIT) {   // issue next-tile loads (in flight during mma)
            uint32_t ad = adst + (b ^ 1) * ABYTES;
            const __half* as = arow + (it + 1) * 32;
            #pragma unroll
            for (int c = 0; c < 4; c++) cpa16(ad + c * 16, as + c * 8);
            CP_COMMIT();
            const float4* bp = bsrc + (size_t)(it + 1) * bstep;
            pb0 = bp[0]; pb1 = bp[1]; pb2 = bp[2]; pb3 = bp[3];
        }
        #pragma unroll
        for (int ks = 0; ks < 2; ks++) {
            uint32_t a[4][4];
            #pragma unroll
            for (int mi = 0; mi < 4; mi++)
                ldsm4(a[mi], aB[b] + mi * (16 * AS * 2) + ks * 32);
            #pragma unroll
            for (int j = 0; j < 4; j++) {
                uint32_t bb[4];
                ldsm4t(bb, bB[b] + ks * (16 * BS * 2) + j * 32);
                #pragma unroll
                for (int mi = 0; mi < 4; mi++) {
                    mma16816(acc[mi][2 * j],     a[mi], bb[0], bb[1]);
                    mma16816(acc[mi][2 * j + 1], a[mi], bb[2], bb[3]);
                }
            }
        }
    }

    // epilogue: relu(acc + b1) -> hbuf (f16)
    #pragma unroll
    for (int mi = 0; mi < 4; mi++) {
        int r = m0 + wm * 64 + mi * 16 + grp;
        bool v0 = (r < M), v1 = (r + 8 < M);
        #pragma unroll
        for (int ni = 0; ni < 8; ni++) {
            int c = n0 + wn * 64 + ni * 8 + t4 * 2;
            float2 bv = *(const float2*)(b1 + (size_t)e * F_DIM + c);
            if (v0) {
                half2 h = __floats2half2_rn(fmaxf(acc[mi][ni][0] + bv.x, 0.f),
                                            fmaxf(acc[mi][ni][1] + bv.y, 0.f));
                *(half2*)(d_hbuf + (size_t)(e * CAP + r) * F_DIM + c) = h;
            }
            if (v1) {
                half2 h = __floats2half2_rn(fmaxf(acc[mi][ni][2] + bv.x, 0.f),
                                            fmaxf(acc[mi][ni][3] + bv.y, 0.f));
                *(half2*)(d_hbuf + (size_t)(e * CAP + r + 8) * F_DIM + c) = h;
            }
        }
    }
}

// ---------------- kernel 3: GEMM2  out[tok] += wt*(h @ W2[e] + b2) ----------------
__global__ __launch_bounds__(256, 1) void moe_ffn2_kernel(
    const float* __restrict__ w2, const float* __restrict__ b2, float* __restrict__ out)
{
    int e  = blockIdx.z;
    int M  = d_cnt[e];
    int m0 = blockIdx.y * BM;
    if (m0 >= M) return;
    int n0 = blockIdx.x * BN;

    extern __shared__ char smem[];
    uint32_t sb = smem_u32(smem);

    int tid = threadIdx.x, warp = tid >> 5, lane = tid & 31;
    int wm = warp >> 1, wn = warp & 1;
    int grp = lane >> 2, t4 = lane & 3;
    int lrow = lane & 15, lsel = lane >> 4;

    int ar = tid;
    const __half* arow = d_hbuf + (size_t)(e * CAP + m0 + ar) * F_DIM;
    uint32_t adst = sb + ar * 80;
    int kl = tid >> 3, nq = (tid & 7) * 16;
    const float4* bsrc = (const float4*)(w2 + ((size_t)e * F_DIM + kl) * H_DIM + n0 + nq);
    const size_t bstep = (size_t)BK * H_DIM / 4;
    __half* bdst = (__half*)(smem + SMB) + kl * BS + nq;

    uint32_t aB[2], bB[2];
    #pragma unroll
    for (int b = 0; b < 2; b++) {
        aB[b] = sb + b * ABYTES + ((wm * 64 + lrow) * AS + lsel * 8) * 2;
        bB[b] = sb + SMB + b * BBYTES + (lrow * BS + wn * 64 + lsel * 8) * 2;
    }

    float acc[4][8][4];
    #pragma unroll
    for (int mi = 0; mi < 4; mi++)
        #pragma unroll
        for (int ni = 0; ni < 8; ni++)
            #pragma unroll
            for (int j = 0; j < 4; j++) acc[mi][ni][j] = 0.f;

    const int NIT = F_DIM / BK;   // 128
    #pragma unroll
    for (int c = 0; c < 4; c++) cpa16(adst + c * 16, arow + c * 8);
    CP_COMMIT();
    float4 pb0 = bsrc[0], pb1 = bsrc[1], pb2 = bsrc[2], pb3 = bsrc[3];

    for (int it = 0; it < NIT; ++it) {
        int b = it & 1;
        {
            uint4 u0 = make_uint4(pk(pb0.x, pb0.y), pk(pb0.z, pb0.w),
                                  pk(pb1.x, pb1.y), pk(pb1.z, pb1.w));
            uint4 u1 = make_uint4(pk(pb2.x, pb2.y), pk(pb2.z, pb2.w),
                                  pk(pb3.x, pb3.y), pk(pb3.z, pb3.w));
            __half* bd = bdst + b * (BBYTES / 2);
            *(uint4*)bd = u0;
            *(uint4*)(bd + 8) = u1;
        }
        CP_WAIT0();
        __syncthreads();
        if (it + 1 < NIT) {
            uint32_t ad = adst + (b ^ 1) * ABYTES;
            const __half* as = arow + (it + 1) * 32;
            #pragma unroll
            for (int c = 0; c < 4; c++) cpa16(ad + c * 16, as + c * 8);
            CP_COMMIT();
            const float4* bp = bsrc + (size_t)(it + 1) * bstep;
            pb0 = bp[0]; pb1 = bp[1]; pb2 = bp[2]; pb3 = bp[3];
        }
        #pragma unroll
        for (int ks = 0; ks < 2; ks++) {
            uint32_t a[4][4];
            #pragma unroll
            for (int mi = 0; mi < 4; mi++)
                ldsm4(a[mi], aB[b] + mi * (16 * AS * 2) + ks * 32);
            #pragma unroll
            for (int j = 0; j < 4; j++) {
                uint32_t bb[4];
                ldsm4t(bb, bB[b] + ks * (16 * BS * 2) + j * 32);
                #pragma unroll
                for (int mi = 0; mi < 4; mi++) {
                    mma16816(acc[mi][2 * j],     a[mi], bb[0], bb[1]);
                    mma16816(acc[mi][2 * j + 1], a[mi], bb[2], bb[3]);
                }
            }
        }
    }

    // epilogue: scatter wt*(acc + b2) into out
    #pragma unroll
    for (int mi = 0; mi < 4; mi++) {
        int r = m0 + wm * 64 + mi * 16 + grp;
        bool v0 = (r < M), v1 = (r + 8 < M);
        int tok0 = 0, tok1 = 0; float wt0 = 0.f, wt1 = 0.f;
        if (v0) { tok0 = d_tok[e * CAP + r];     wt0 = d_wt[e * CAP + r]; }
        if (v1) { tok1 = d_tok[e * CAP + r + 8]; wt1 = d_wt[e * CAP + r + 8]; }
        #pragma unroll
        for (int ni = 0; ni < 8; ni++) {
            int c = n0 + wn * 64 + ni * 8 + t4 * 2;
            float2 bv = *(const float2*)(b2 + (size_t)e * H_DIM + c);
            if (v0) {
                atomicAdd(out + (size_t)tok0 * H_DIM + c,     wt0 * (acc[mi][ni][0] + bv.x));
                atomicAdd(out + (size_t)tok0 * H_DIM + c + 1, wt0 * (acc[mi][ni][1] + bv.y));
            }
            if (v1) {
                atomicAdd(out + (size_t)tok1 * H_DIM + c,     wt1 * (acc[mi][ni][2] + bv.x));
                atomicAdd(out + (size_t)tok1 * H_DIM + c + 1, wt1 * (acc[mi][ni][3] + bv.y));
            }
        }
    }
}

// ---------------- launch ----------------
extern "C" void kernel_launch(void* const* d_in, const int* in_sizes, int n_in,
                              void* d_out, int out_size) {
    const float* x  = (const float*)d_in[0];
    const float* gw = (const float*)d_in[1];
    const float* gb = (const float*)d_in[2];
    const float* w1 = (const float*)d_in[3];
    const float* b1 = (const float*)d_in[4];
    const float* w2 = (const float*)d_in[5];
    const float* b2 = (const float*)d_in[6];
    float* out = (float*)d_out;

    static bool attr_done = false;
    if (!attr_done) {
        cudaFuncSetAttribute(moe_ffn1_kernel, cudaFuncAttributeMaxDynamicSharedMemorySize, SMEM_TOTAL);
        cudaFuncSetAttribute(moe_ffn2_kernel, cudaFuncAttributeMaxDynamicSharedMemorySize, SMEM_TOTAL);
        attr_done = true;
    }

    moe_zero_kernel<<<512, 256>>>((const float4*)x, (float4*)d_out);
    moe_router_kernel<<<T_TOK / 8, 256>>>(x, gw, gb);
    dim3 g1(F_DIM / BN, CAP / BM, E_NUM);
    moe_ffn1_kernel<<<g1, 256, SMEM_TOTAL>>>(w1, b1);
    dim3 g2(H_DIM / BN, CAP / BM, E_NUM);
    moe_ffn2_kernel<<<g2, 256, SMEM_TOTAL>>>(w2, b2, out);
}

// round 6
// speedup vs baseline: 1.4953x; 1.4953x over previous
#include <cuda_runtime.h>
#include <cuda_fp16.h>
#include <math.h>
#include <stdint.h>

// ---------------- problem dims ----------------
#define T_TOK 2048
#define H_DIM 1024
#define F_DIM 4096
#define E_NUM 8
#define CAP   2048

// ---------------- GEMM tiling ----------------
#define BM 128
#define BN 128
#define BK 32
#define AS 40      // A row stride (halves), 80B: ldsm conflict-free
#define BS 136     // B row stride (halves), 272B: ldsm conflict-free

#define ABYTES (BM * AS * 2)     // 10240
#define BBYTES (BK * BS * 2)     // 8704

// ---------------- device scratch ----------------
__device__ int    d_cnt[E_NUM];
__device__ int    d_tok[E_NUM * CAP];
__device__ float  d_wt [E_NUM * CAP];
__device__ __half d_x16[T_TOK * H_DIM];
__device__ __half d_hbuf[(size_t)E_NUM * CAP * F_DIM];   // h in f16

// ---------------- helpers ----------------
__device__ __forceinline__ uint32_t smem_u32(const void* p) {
    uint32_t a;
    asm("{ .reg .u64 t; cvta.to.shared.u64 t, %1; cvt.u32.u64 %0, t; }" : "=r"(a) : "l"(p));
    return a;
}
__device__ __forceinline__ void ldsm4(uint32_t r[4], uint32_t addr) {
    asm volatile("ldmatrix.sync.aligned.m8n8.x4.shared.b16 {%0,%1,%2,%3}, [%4];"
                 : "=r"(r[0]), "=r"(r[1]), "=r"(r[2]), "=r"(r[3]) : "r"(addr));
}
__device__ __forceinline__ void ldsm4t(uint32_t r[4], uint32_t addr) {
    asm volatile("ldmatrix.sync.aligned.m8n8.x4.trans.shared.b16 {%0,%1,%2,%3}, [%4];"
                 : "=r"(r[0]), "=r"(r[1]), "=r"(r[2]), "=r"(r[3]) : "r"(addr));
}
__device__ __forceinline__ void mma16816(float c[4], const uint32_t a[4],
                                         uint32_t b0, uint32_t b1) {
    asm volatile(
        "mma.sync.aligned.m16n8k16.row.col.f32.f16.f16.f32 "
        "{%0,%1,%2,%3}, {%4,%5,%6,%7}, {%8,%9}, {%0,%1,%2,%3};\n"
        : "+f"(c[0]), "+f"(c[1]), "+f"(c[2]), "+f"(c[3])
        : "r"(a[0]), "r"(a[1]), "r"(a[2]), "r"(a[3]), "r"(b0), "r"(b1));
}
__device__ __forceinline__ void cpa16(uint32_t dst, const void* src) {
    asm volatile("cp.async.ca.shared.global [%0], [%1], 16;" :: "r"(dst), "l"(src));
}
#define CP_COMMIT() asm volatile("cp.async.commit_group;" ::: "memory")
#define CP_WAIT0()  asm volatile("cp.async.wait_group 0;" ::: "memory")
__device__ __forceinline__ uint32_t pk(float a, float b) {
    half2 h = __floats2half2_rn(a, b);
    return *(uint32_t*)&h;
}

// ---------------- kernel 0: zero out + counters + convert x -> f16 ----------------
__global__ void moe_zero_kernel(const float4* __restrict__ x, float4* __restrict__ out) {
    int i = blockIdx.x * blockDim.x + threadIdx.x;
    if (i < E_NUM) d_cnt[i] = 0;
    int stride = gridDim.x * blockDim.x;
    for (int j = i; j < T_TOK * H_DIM / 4; j += stride) {
        out[j] = make_float4(0.f, 0.f, 0.f, 0.f);
        float4 v = x[j];
        uint2 u = make_uint2(pk(v.x, v.y), pk(v.z, v.w));
        *(uint2*)(d_x16 + (size_t)j * 4) = u;
    }
}

// ---------------- kernel 1: router (warp per token) ----------------
__global__ __launch_bounds__(256) void moe_router_kernel(
    const float* __restrict__ x, const float* __restrict__ gw, const float* __restrict__ gb)
{
    int t = blockIdx.x * 8 + (threadIdx.x >> 5);
    int lane = threadIdx.x & 31;
    if (t >= T_TOK) return;
    float s[E_NUM];
    #pragma unroll
    for (int e = 0; e < E_NUM; e++) s[e] = 0.f;
    #pragma unroll 4
    for (int j = 0; j < H_DIM / 32; j++) {
        float xv = x[(size_t)t * H_DIM + j * 32 + lane];
        const float4* g = (const float4*)(gw + (size_t)(j * 32 + lane) * E_NUM);
        float4 g0 = g[0], g1 = g[1];
        s[0] += xv * g0.x; s[1] += xv * g0.y; s[2] += xv * g0.z; s[3] += xv * g0.w;
        s[4] += xv * g1.x; s[5] += xv * g1.y; s[6] += xv * g1.z; s[7] += xv * g1.w;
    }
    #pragma unroll
    for (int e = 0; e < E_NUM; e++) {
        #pragma unroll
        for (int o = 16; o; o >>= 1) s[e] += __shfl_xor_sync(0xffffffffu, s[e], o);
    }
    if (lane == 0) {
        float lg[E_NUM];
        #pragma unroll
        for (int e = 0; e < E_NUM; e++) lg[e] = s[e] + gb[e];
        int i1 = 0; float l1 = lg[0];
        #pragma unroll
        for (int e = 1; e < E_NUM; e++) if (lg[e] > l1) { l1 = lg[e]; i1 = e; }
        int i2 = -1; float l2 = -1e30f;
        #pragma unroll
        for (int e = 0; e < E_NUM; e++) if (e != i1 && lg[e] > l2) { l2 = lg[e]; i2 = e; }
        float p1 = 1.0f / (1.0f + expf(l2 - l1));
        float p2 = 1.0f - p1;
        int q1 = atomicAdd(&d_cnt[i1], 1);
        d_tok[i1 * CAP + q1] = t;  d_wt[i1 * CAP + q1] = p1;
        int q2 = atomicAdd(&d_cnt[i2], 1);
        d_tok[i2 * CAP + q2] = t;  d_wt[i2 * CAP + q2] = p2;
    }
}

// ================= shared GEMM body =================
// 128 threads, CTA 128x128x32, 4 warps (2x2) of 64x64.
// A via cp.async (f16 gmem), B via reg prefetch + packed STS, double buffered.
// B thread mapping: brow = tid>>3 (k rows brow, brow+16), c16 = tid&7.
// Pair p of pb (p=0..3): row brow + (p>=2 ? 16 : 0), col block c16*8 + (p&1 ? 64 : 0).
#define PB_IDX(c) ((c & 1) + ((c >> 1) & 1) * 16 + ((c >= 4) ? 16 * (size_t)BS0 : 0))
#define GEMM_BODY(NIT, AROW_PTR, BSRC, BSTEP)                                         \
    __shared__ __half As[2 * BM * AS];                                                \
    __shared__ __half Bs[2 * BK * BS];                                                \
    uint32_t sA = smem_u32(As), sB = smem_u32(Bs);                                    \
    int tid = threadIdx.x, warp = tid >> 5, lane = tid & 31;                          \
    int wm = warp >> 1, wn = warp & 1;                                                \
    int grp = lane >> 2, t4 = lane & 3;                                               \
    int lrow = lane & 15, lsel = lane >> 4;                                           \
    uint32_t adst = sA + tid * 80;                                                    \
    int brow = tid >> 3, c16 = tid & 7;                                               \
    const float4* bsrc = (BSRC);                                                      \
    __half* bd0 = Bs + brow * BS + c16 * 8;                                           \
    uint32_t aB[2], bB[2];                                                            \
    _Pragma("unroll")                                                                 \
    for (int b = 0; b < 2; b++) {                                                     \
        aB[b] = sA + b * ABYTES + ((wm * 64 + lrow) * AS + lsel * 8) * 2;             \
        bB[b] = sB + b * BBYTES + (lrow * BS + wn * 64 + lsel * 8) * 2;               \
    }                                                                                 \
    float acc[4][8][4];                                                               \
    _Pragma("unroll")                                                                 \
    for (int mi = 0; mi < 4; mi++)                                                    \
        _Pragma("unroll")                                                             \
        for (int ni = 0; ni < 8; ni++)                                                \
            _Pragma("unroll")                                                         \
            for (int j = 0; j < 4; j++) acc[mi][ni][j] = 0.f;                         \
    _Pragma("unroll")                                                                 \
    for (int c = 0; c < 4; c++) cpa16(adst + c * 16, (AROW_PTR) + c * 8);             \
    CP_COMMIT();                                                                      \
    float4 pb[8];                                                                     \
    _Pragma("unroll")                                                                 \
    for (int c = 0; c < 8; c++) pb[c] = bsrc[PB_IDX(c)];                              \
    for (int it = 0; it < (NIT); ++it) {                                              \
        int b = it & 1;                                                               \
        { /* packed B stores: pair h -> col block (h&1)*64, row +16 if h>=2 */        \
            __half* bd = bd0 + b * (BK * BS);                                         \
            _Pragma("unroll")                                                         \
            for (int h = 0; h < 4; h++) {                                             \
                uint4 u = make_uint4(pk(pb[2*h].x, pb[2*h].y), pk(pb[2*h].z, pb[2*h].w), \
                                     pk(pb[2*h+1].x, pb[2*h+1].y), pk(pb[2*h+1].z, pb[2*h+1].w)); \
                *(uint4*)(bd + (h & 1) * 64 + ((h >= 2) ? 16 * BS : 0)) = u;          \
            }                                                                         \
        }                                                                             \
        CP_WAIT0();                                                                   \
        __syncthreads();                                                              \
        if (it + 1 < (NIT)) {                                                         \
            uint32_t ad = adst + (b ^ 1) * ABYTES;                                    \
            const __half* as = (AROW_PTR) + (it + 1) * 32;                            \
            _Pragma("unroll")                                                         \
            for (int c = 0; c < 4; c++) cpa16(ad + c * 16, as + c * 8);               \
            CP_COMMIT();                                                              \
            const float4* bp = bsrc + (size_t)(it + 1) * (BSTEP);                     \
            _Pragma("unroll")                                                         \
            for (int c = 0; c < 8; c++) pb[c] = bp[PB_IDX(c)];                        \
        }                                                                             \
        _Pragma("unroll")                                                             \
        for (int ks = 0; ks < 2; ks++) {                                              \
            uint32_t a[4][4];                                                         \
            _Pragma("unroll")                                                         \
            for (int mi = 0; mi < 4; mi++)                                            \
                ldsm4(a[mi], aB[b] + mi * (16 * AS * 2) + ks * 32);                   \
            _Pragma("unroll")                                                         \
            for (int j = 0; j < 4; j++) {                                             \
                uint32_t bb[4];                                                       \
                ldsm4t(bb, bB[b] + ks * (16 * BS * 2) + j * 32);                      \
                _Pragma("unroll")                                                     \
                for (int mi = 0; mi < 4; mi++) {                                      \
                    mma16816(acc[mi][2 * j],     a[mi], bb[0], bb[1]);                \
                    mma16816(acc[mi][2 * j + 1], a[mi], bb[2], bb[3]);                \
                }                                                                     \
            }                                                                         \
        }                                                                             \
    }

// ---------------- kernel 2: GEMM1  h = relu(X_gather @ W1[e] + b1) ----------------
__global__ __launch_bounds__(128, 2) void moe_ffn1_kernel(
    const float* __restrict__ w1, const float* __restrict__ b1)
{
    int e  = blockIdx.z;
    int M  = d_cnt[e];
    int m0 = blockIdx.y * BM;
    if (m0 >= M) return;
    int n0 = blockIdx.x * BN;

    int gr = m0 + threadIdx.x;
    int tokA = d_tok[e * CAP + ((gr < M) ? gr : 0)];
    const __half* arow = d_x16 + (size_t)tokA * H_DIM;
    #define BS0 (F_DIM / 4)
    const float4* bsrc_init = (const float4*)(w1 + ((size_t)e * H_DIM + (threadIdx.x >> 3)) * F_DIM
                                              + n0 + (threadIdx.x & 7) * 8);
    GEMM_BODY(H_DIM / BK, arow, bsrc_init, (size_t)BK * F_DIM / 4)
    #undef BS0

    // epilogue: relu(acc + b1) -> hbuf (f16)
    #pragma unroll
    for (int mi = 0; mi < 4; mi++) {
        int r = m0 + wm * 64 + mi * 16 + grp;
        bool v0 = (r < M), v1 = (r + 8 < M);
        #pragma unroll
        for (int ni = 0; ni < 8; ni++) {
            int c = n0 + wn * 64 + ni * 8 + t4 * 2;
            float2 bv = *(const float2*)(b1 + (size_t)e * F_DIM + c);
            if (v0) {
                half2 h = __floats2half2_rn(fmaxf(acc[mi][ni][0] + bv.x, 0.f),
                                            fmaxf(acc[mi][ni][1] + bv.y, 0.f));
                *(half2*)(d_hbuf + (size_t)(e * CAP + r) * F_DIM + c) = h;
            }
            if (v1) {
                half2 h = __floats2half2_rn(fmaxf(acc[mi][ni][2] + bv.x, 0.f),
                                            fmaxf(acc[mi][ni][3] + bv.y, 0.f));
                *(half2*)(d_hbuf + (size_t)(e * CAP + r + 8) * F_DIM + c) = h;
            }
        }
    }
}

// ---------------- kernel 3: GEMM2  out[tok] += wt*(h @ W2[e] + b2) ----------------
__global__ __launch_bounds__(128, 2) void moe_ffn2_kernel(
    const float* __restrict__ w2, const float* __restrict__ b2, float* __restrict__ out)
{
    int e  = blockIdx.z;
    int M  = d_cnt[e];
    int m0 = blockIdx.y * BM;
    if (m0 >= M) return;
    int n0 = blockIdx.x * BN;

    const __half* arow = d_hbuf + (size_t)(e * CAP + m0 + threadIdx.x) * F_DIM;
    #define BS0 (H_DIM / 4)
    const float4* bsrc_init = (const float4*)(w2 + ((size_t)e * F_DIM + (threadIdx.x >> 3)) * H_DIM
                                              + n0 + (threadIdx.x & 7) * 8);
    GEMM_BODY(F_DIM / BK, arow, bsrc_init, (size_t)BK * H_DIM / 4)
    #undef BS0

    // epilogue: scatter wt*(acc + b2) into out
    #pragma unroll
    for (int mi = 0; mi < 4; mi++) {
        int r = m0 + wm * 64 + mi * 16 + grp;
        bool v0 = (r < M), v1 = (r + 8 < M);
        int tok0 = 0, tok1 = 0; float wt0 = 0.f, wt1 = 0.f;
        if (v0) { tok0 = d_tok[e * CAP + r];     wt0 = d_wt[e * CAP + r]; }
        if (v1) { tok1 = d_tok[e * CAP + r + 8]; wt1 = d_wt[e * CAP + r + 8]; }
        #pragma unroll
        for (int ni = 0; ni < 8; ni++) {
            int c = n0 + wn * 64 + ni * 8 + t4 * 2;
            float2 bv = *(const float2*)(b2 + (size_t)e * H_DIM + c);
            if (v0) {
                atomicAdd(out + (size_t)tok0 * H_DIM + c,     wt0 * (acc[mi][ni][0] + bv.x));
                atomicAdd(out + (size_t)tok0 * H_DIM + c + 1, wt0 * (acc[mi][ni][1] + bv.y));
            }
            if (v1) {
                atomicAdd(out + (size_t)tok1 * H_DIM + c,     wt1 * (acc[mi][ni][2] + bv.x));
                atomicAdd(out + (size_t)tok1 * H_DIM + c + 1, wt1 * (acc[mi][ni][3] + bv.y));
            }
        }
    }
}

// ---------------- launch ----------------
extern "C" void kernel_launch(void* const* d_in, const int* in_sizes, int n_in,
                              void* d_out, int out_size) {
    const float* x  = (const float*)d_in[0];
    const float* gw = (const float*)d_in[1];
    const float* gb = (const float*)d_in[2];
    const float* w1 = (const float*)d_in[3];
    const float* b1 = (const float*)d_in[4];
    const float* w2 = (const float*)d_in[5];
    const float* b2 = (const float*)d_in[6];
    float* out = (float*)d_out;

    moe_zero_kernel<<<512, 256>>>((const float4*)x, (float4*)d_out);
    moe_router_kernel<<<T_TOK / 8, 256>>>(x, gw, gb);
    dim3 g1(F_DIM / BN, CAP / BM, E_NUM);
    moe_ffn1_kernel<<<g1, 128>>>(w1, b1);
    dim3 g2(H_DIM / BN, CAP / BM, E_NUM);
    moe_ffn2_kernel<<<g2, 128>>>(w2, b2, out);
}

// round 7
// speedup vs baseline: 1.7618x; 1.1782x over previous
#include <cuda_runtime.h>
#include <cuda_fp16.h>
#include <math.h>
#include <stdint.h>

// ---------------- problem dims ----------------
#define T_TOK 2048
#define H_DIM 1024
#define F_DIM 4096
#define E_NUM 8
#define CAP   2048

// ---------------- GEMM tiling ----------------
#define BM 128
#define BN 128
#define BK 32
#define AS 40      // A row stride (halves), 80B: ldsm conflict-free
#define BS 136     // B row stride (halves), 272B: ldsm conflict-free
#define STAGES 3

#define ABYTES (BM * AS * 2)              // 10240
#define BBYTES (BK * BS * 2)              // 8704
#define STAGE_BYTES (ABYTES + BBYTES)     // 18944
#define SMEM_TOTAL (STAGES * STAGE_BYTES) // 56832  (dynamic)
#define SMB (STAGES * ABYTES)             // B region offset

// ---------------- device scratch ----------------
__device__ int    d_cnt[E_NUM];
__device__ int    d_tok[E_NUM * CAP];
__device__ float  d_wt [E_NUM * CAP];
__device__ __half d_x16[T_TOK * H_DIM];
__device__ __half d_w1h[(size_t)E_NUM * H_DIM * F_DIM];   // 67 MB
__device__ __half d_w2h[(size_t)E_NUM * F_DIM * H_DIM];   // 67 MB
__device__ __half d_hbuf[(size_t)E_NUM * CAP * F_DIM];    // 128 MB

// ---------------- helpers ----------------
__device__ __forceinline__ uint32_t smem_u32(const void* p) {
    uint32_t a;
    asm("{ .reg .u64 t; cvta.to.shared.u64 t, %1; cvt.u32.u64 %0, t; }" : "=r"(a) : "l"(p));
    return a;
}
__device__ __forceinline__ void ldsm4(uint32_t r[4], uint32_t addr) {
    asm volatile("ldmatrix.sync.aligned.m8n8.x4.shared.b16 {%0,%1,%2,%3}, [%4];"
                 : "=r"(r[0]), "=r"(r[1]), "=r"(r[2]), "=r"(r[3]) : "r"(addr));
}
__device__ __forceinline__ void ldsm4t(uint32_t r[4], uint32_t addr) {
    asm volatile("ldmatrix.sync.aligned.m8n8.x4.trans.shared.b16 {%0,%1,%2,%3}, [%4];"
                 : "=r"(r[0]), "=r"(r[1]), "=r"(r[2]), "=r"(r[3]) : "r"(addr));
}
__device__ __forceinline__ void mma16816(float c[4], const uint32_t a[4],
                                         uint32_t b0, uint32_t b1) {
    asm volatile(
        "mma.sync.aligned.m16n8k16.row.col.f32.f16.f16.f32 "
        "{%0,%1,%2,%3}, {%4,%5,%6,%7}, {%8,%9}, {%0,%1,%2,%3};\n"
        : "+f"(c[0]), "+f"(c[1]), "+f"(c[2]), "+f"(c[3])
        : "r"(a[0]), "r"(a[1]), "r"(a[2]), "r"(a[3]), "r"(b0), "r"(b1));
}
__device__ __forceinline__ void cpa16(uint32_t dst, const void* src) {
    asm volatile("cp.async.ca.shared.global [%0], [%1], 16;" :: "r"(dst), "l"(src));
}
#define CP_COMMIT() asm volatile("cp.async.commit_group;" ::: "memory")
#define CP_WAIT1()  asm volatile("cp.async.wait_group 1;" ::: "memory")
__device__ __forceinline__ uint32_t pk(float a, float b) {
    half2 h = __floats2half2_rn(a, b);
    return *(uint32_t*)&h;
}

// ---------------- kernel 0: prep (zero out/cnt, convert x/w1/w2 -> f16) ----------------
__global__ void moe_prep_kernel(const float4* __restrict__ x,
                                const float4* __restrict__ w1,
                                const float4* __restrict__ w2,
                                float4* __restrict__ out) {
    int i = blockIdx.x * blockDim.x + threadIdx.x;
    int stride = gridDim.x * blockDim.x;
    if (i < E_NUM) d_cnt[i] = 0;
    // x convert + out zero (0.5M float4)
    for (int j = i; j < T_TOK * H_DIM / 4; j += stride) {
        out[j] = make_float4(0.f, 0.f, 0.f, 0.f);
        float4 v = x[j];
        *(uint2*)(d_x16 + (size_t)j * 4) = make_uint2(pk(v.x, v.y), pk(v.z, v.w));
    }
    // w1 convert (8.4M float4)
    const size_t NW = (size_t)E_NUM * H_DIM * F_DIM / 4;
    for (size_t j = i; j < NW; j += stride) {
        float4 v = w1[j];
        *(uint2*)(d_w1h + j * 4) = make_uint2(pk(v.x, v.y), pk(v.z, v.w));
    }
    // w2 convert (8.4M float4)
    for (size_t j = i; j < NW; j += stride) {
        float4 v = w2[j];
        *(uint2*)(d_w2h + j * 4) = make_uint2(pk(v.x, v.y), pk(v.z, v.w));
    }
}

// ---------------- kernel 1: router (warp per token) ----------------
__global__ __launch_bounds__(256) void moe_router_kernel(
    const float* __restrict__ x, const float* __restrict__ gw, const float* __restrict__ gb)
{
    int t = blockIdx.x * 8 + (threadIdx.x >> 5);
    int lane = threadIdx.x & 31;
    if (t >= T_TOK) return;
    float s[E_NUM];
    #pragma unroll
    for (int e = 0; e < E_NUM; e++) s[e] = 0.f;
    #pragma unroll 4
    for (int j = 0; j < H_DIM / 32; j++) {
        float xv = x[(size_t)t * H_DIM + j * 32 + lane];
        const float4* g = (const float4*)(gw + (size_t)(j * 32 + lane) * E_NUM);
        float4 g0 = g[0], g1 = g[1];
        s[0] += xv * g0.x; s[1] += xv * g0.y; s[2] += xv * g0.z; s[3] += xv * g0.w;
        s[4] += xv * g1.x; s[5] += xv * g1.y; s[6] += xv * g1.z; s[7] += xv * g1.w;
    }
    #pragma unroll
    for (int e = 0; e < E_NUM; e++) {
        #pragma unroll
        for (int o = 16; o; o >>= 1) s[e] += __shfl_xor_sync(0xffffffffu, s[e], o);
    }
    if (lane == 0) {
        float lg[E_NUM];
        #pragma unroll
        for (int e = 0; e < E_NUM; e++) lg[e] = s[e] + gb[e];
        int i1 = 0; float l1 = lg[0];
        #pragma unroll
        for (int e = 1; e < E_NUM; e++) if (lg[e] > l1) { l1 = lg[e]; i1 = e; }
        int i2 = -1; float l2 = -1e30f;
        #pragma unroll
        for (int e = 0; e < E_NUM; e++) if (e != i1 && lg[e] > l2) { l2 = lg[e]; i2 = e; }
        float p1 = 1.0f / (1.0f + expf(l2 - l1));
        float p2 = 1.0f - p1;
        int q1 = atomicAdd(&d_cnt[i1], 1);
        d_tok[i1 * CAP + q1] = t;  d_wt[i1 * CAP + q1] = p1;
        int q2 = atomicAdd(&d_cnt[i2], 1);
        d_tok[i2 * CAP + q2] = t;  d_wt[i2 * CAP + q2] = p2;
    }
}

// ================= shared async-pipelined GEMM body =================
// 128 threads, CTA 128x128x32, 4 warps (2x2) of 64x64; 3-stage cp.async.
// A thread map: row = tid, 4x16B chunks along k.
// B thread map: brow = tid>>2 (k-row 0..31), bc = tid&3; chunks bc + c*4 (c=0..3).
#define LOAD_STAGE(s, buf)                                                             \
    do {                                                                               \
        if ((s) < NIT) {                                                               \
            uint32_t ad = sA + (buf) * ABYTES + tid * 80;                              \
            const __half* as_ = arow + (s) * 32;                                       \
            _Pragma("unroll")                                                          \
            for (int c = 0; c < 4; c++) cpa16(ad + c * 16, as_ + c * 8);               \
            uint32_t bdst = sB + (buf) * BBYTES + (brow * BS) * 2 + bc * 16;           \
            const __half* bs_ = bthr + (size_t)(s) * 32 * BGST;                        \
            _Pragma("unroll")                                                          \
            for (int c = 0; c < 4; c++) cpa16(bdst + c * 64, bs_ + c * 32);            \
        }                                                                              \
        CP_COMMIT();                                                                   \
    } while (0)

#define GEMM_BODY(NIT_, AROW_PTR, BBASE, BGST_)                                        \
    extern __shared__ char smem[];                                                     \
    const int NIT = (NIT_);                                                            \
    const int BGST = (BGST_);                                                          \
    uint32_t sA = smem_u32(smem), sB = sA + SMB;                                       \
    int tid = threadIdx.x, warp = tid >> 5, lane = tid & 31;                           \
    int wm = warp >> 1, wn = warp & 1;                                                 \
    int grp = lane >> 2, t4 = lane & 3;                                                \
    int lrow = lane & 15, lsel = lane >> 4;                                            \
    const __half* arow = (AROW_PTR);                                                   \
    int brow = tid >> 2, bc = tid & 3;                                                 \
    const __half* bthr = (BBASE) + (size_t)brow * BGST + bc * 8;                       \
    uint32_t aF = sA + ((wm * 64 + lrow) * AS + lsel * 8) * 2;                         \
    uint32_t bF = sB + (lrow * BS + wn * 64 + lsel * 8) * 2;                           \
    float acc[4][8][4];                                                                \
    _Pragma("unroll")                                                                  \
    for (int mi = 0; mi < 4; mi++)                                                     \
        _Pragma("unroll")                                                              \
        for (int ni = 0; ni < 8; ni++)                                                 \
            _Pragma("unroll")                                                          \
            for (int j = 0; j < 4; j++) acc[mi][ni][j] = 0.f;                          \
    LOAD_STAGE(0, 0);                                                                  \
    LOAD_STAGE(1, 1);                                                                  \
    int buf = 0, nbuf = 2;                                                             \
    for (int it = 0; it < NIT; ++it) {                                                 \
        CP_WAIT1();                                                                    \
        __syncthreads();                                                               \
        LOAD_STAGE(it + 2, nbuf);                                                      \
        uint32_t aB = aF + buf * ABYTES, bB = bF + buf * BBYTES;                       \
        _Pragma("unroll")                                                              \
        for (int ks = 0; ks < 2; ks++) {                                               \
            uint32_t a[4][4];                                                          \
            _Pragma("unroll")                                                          \
            for (int mi = 0; mi < 4; mi++)                                             \
                ldsm4(a[mi], aB + mi * (16 * AS * 2) + ks * 32);                       \
            _Pragma("unroll")                                                          \
            for (int j = 0; j < 4; j++) {                                              \
                uint32_t bb[4];                                                        \
                ldsm4t(bb, bB + ks * (16 * BS * 2) + j * 32);                          \
                _Pragma("unroll")                                                      \
                for (int mi = 0; mi < 4; mi++) {                                       \
                    mma16816(acc[mi][2 * j],     a[mi], bb[0], bb[1]);                 \
                    mma16816(acc[mi][2 * j + 1], a[mi], bb[2], bb[3]);                 \
                }                                                                      \
            }                                                                          \
        }                                                                              \
        buf = (buf == STAGES - 1) ? 0 : buf + 1;                                       \
        nbuf = (nbuf == STAGES - 1) ? 0 : nbuf + 1;                                    \
    }

// ---------------- kernel 2: GEMM1  h = relu(X_gather @ W1[e] + b1) ----------------
__global__ __launch_bounds__(128, 2) void moe_ffn1_kernel(const float* __restrict__ b1)
{
    int e  = blockIdx.z;
    int M  = d_cnt[e];
    int m0 = blockIdx.y * BM;
    if (m0 >= M) return;
    int n0 = blockIdx.x * BN;

    int gr = m0 + threadIdx.x;
    int tokA = d_tok[e * CAP + ((gr < M) ? gr : 0)];
    GEMM_BODY(H_DIM / BK,
              d_x16 + (size_t)tokA * H_DIM,
              d_w1h + (size_t)e * H_DIM * F_DIM + n0,
              F_DIM)

    // epilogue: relu(acc + b1) -> hbuf (f16)
    #pragma unroll
    for (int mi = 0; mi < 4; mi++) {
        int r = m0 + wm * 64 + mi * 16 + grp;
        bool v0 = (r < M), v1 = (r + 8 < M);
        #pragma unroll
        for (int ni = 0; ni < 8; ni++) {
            int c = n0 + wn * 64 + ni * 8 + t4 * 2;
            float2 bv = *(const float2*)(b1 + (size_t)e * F_DIM + c);
            if (v0) {
                half2 h = __floats2half2_rn(fmaxf(acc[mi][ni][0] + bv.x, 0.f),
                                            fmaxf(acc[mi][ni][1] + bv.y, 0.f));
                *(half2*)(d_hbuf + (size_t)(e * CAP + r) * F_DIM + c) = h;
            }
            if (v1) {
                half2 h = __floats2half2_rn(fmaxf(acc[mi][ni][2] + bv.x, 0.f),
                                            fmaxf(acc[mi][ni][3] + bv.y, 0.f));
                *(half2*)(d_hbuf + (size_t)(e * CAP + r + 8) * F_DIM + c) = h;
            }
        }
    }
}

// ---------------- kernel 3: GEMM2  out[tok] += wt*(h @ W2[e] + b2) ----------------
__global__ __launch_bounds__(128, 2) void moe_ffn2_kernel(const float* __restrict__ b2,
                                                          float* __restrict__ out)
{
    int e  = blockIdx.z;
    int M  = d_cnt[e];
    int m0 = blockIdx.y * BM;
    if (m0 >= M) return;
    int n0 = blockIdx.x * BN;

    GEMM_BODY(F_DIM / BK,
              d_hbuf + (size_t)(e * CAP + m0 + threadIdx.x) * F_DIM,
              d_w2h + (size_t)e * F_DIM * H_DIM + n0,
              H_DIM)

    // epilogue: scatter wt*(acc + b2) into out
    #pragma unroll
    for (int mi = 0; mi < 4; mi++) {
        int r = m0 + wm * 64 + mi * 16 + grp;
        bool v0 = (r < M), v1 = (r + 8 < M);
        int tok0 = 0, tok1 = 0; float wt0 = 0.f, wt1 = 0.f;
        if (v0) { tok0 = d_tok[e * CAP + r];     wt0 = d_wt[e * CAP + r]; }
        if (v1) { tok1 = d_tok[e * CAP + r + 8]; wt1 = d_wt[e * CAP + r + 8]; }
        #pragma unroll
        for (int ni = 0; ni < 8; ni++) {
            int c = n0 + wn * 64 + ni * 8 + t4 * 2;
            float2 bv = *(const float2*)(b2 + (size_t)e * H_DIM + c);
            if (v0) {
                atomicAdd(out + (size_t)tok0 * H_DIM + c,     wt0 * (acc[mi][ni][0] + bv.x));
                atomicAdd(out + (size_t)tok0 * H_DIM + c + 1, wt0 * (acc[mi][ni][1] + bv.y));
            }
            if (v1) {
                atomicAdd(out + (size_t)tok1 * H_DIM + c,     wt1 * (acc[mi][ni][2] + bv.x));
                atomicAdd(out + (size_t)tok1 * H_DIM + c + 1, wt1 * (acc[mi][ni][3] + bv.y));
            }
        }
    }
}

// ---------------- launch ----------------
extern "C" void kernel_launch(void* const* d_in, const int* in_sizes, int n_in,
                              void* d_out, int out_size) {
    const float* x  = (const float*)d_in[0];
    const float* gw = (const float*)d_in[1];
    const float* gb = (const float*)d_in[2];
    const float* w1 = (const float*)d_in[3];
    const float* b1 = (const float*)d_in[4];
    const float* w2 = (const float*)d_in[5];
    const float* b2 = (const float*)d_in[6];
    float* out = (float*)d_out;

    cudaFuncSetAttribute(moe_ffn1_kernel, cudaFuncAttributeMaxDynamicSharedMemorySize, SMEM_TOTAL);
    cudaFuncSetAttribute(moe_ffn2_kernel, cudaFuncAttributeMaxDynamicSharedMemorySize, SMEM_TOTAL);

    moe_prep_kernel<<<2048, 256>>>((const float4*)x, (const float4*)w1,
                                   (const float4*)w2, (float4*)d_out);
    moe_router_kernel<<<T_TOK / 8, 256>>>(x, gw, gb);
    dim3 g1(F_DIM / BN, CAP / BM, E_NUM);
    moe_ffn1_kernel<<<g1, 128, SMEM_TOTAL>>>(b1);
    dim3 g2(H_DIM / BN, CAP / BM, E_NUM);
    moe_ffn2_kernel<<<g2, 128, SMEM_TOTAL>>>(b2, out);
}

// round 9
// speedup vs baseline: 2.1622x; 1.2273x over previous
#include <cuda_runtime.h>
#include <cuda_fp16.h>
#include <math.h>
#include <stdint.h>

// ---------------- problem dims ----------------
#define T_TOK 2048
#define H_DIM 1024
#define F_DIM 4096
#define E_NUM 8
#define CAP   2048

#define RT_CAP 128      // CAP/16
#define CT1    64       // H/16  : ffn1 A k-tiles
#define NT1    256      // F/16  : ffn1 B n-tiles
#define CT2    256      // F/16  : ffn2 A k-tiles
#define NT2    64       // H/16  : ffn2 B n-tiles

// ---------------- device scratch (fragment-packed: 16B/lane per 16x16 tile) ----------------
__device__ int   d_cnt[E_NUM];
__device__ int   d_tok[E_NUM * CAP];
__device__ float d_wt [E_NUM * CAP];
__device__ uint4 d_xg [(size_t)E_NUM * RT_CAP * CT1 * 32];   // 32 MB  A-frags for ffn1
__device__ uint4 d_w1f[(size_t)E_NUM * CT1 * NT1 * 32];      // 64 MB  B-frags for ffn1
__device__ uint4 d_w2f[(size_t)E_NUM * CT2 * NT2 * 32];      // 64 MB  B-frags for ffn2
__device__ uint4 d_hf [(size_t)E_NUM * RT_CAP * CT2 * 32];   // 128 MB A-frags for ffn2

// ---------------- helpers ----------------
__device__ __forceinline__ void mma16816(float c[4], const uint32_t a[4],
                                         uint32_t b0, uint32_t b1) {
    asm volatile(
        "mma.sync.aligned.m16n8k16.row.col.f32.f16.f16.f32 "
        "{%0,%1,%2,%3}, {%4,%5,%6,%7}, {%8,%9}, {%0,%1,%2,%3};\n"
        : "+f"(c[0]), "+f"(c[1]), "+f"(c[2]), "+f"(c[3])
        : "r"(a[0]), "r"(a[1]), "r"(a[2]), "r"(a[3]), "r"(b0), "r"(b1));
}
__device__ __forceinline__ uint32_t pk(float a, float b) {
    half2 h = __floats2half2_rn(a, b);
    return *(uint32_t*)&h;
}
__device__ __forceinline__ void ldg128(uint32_t r[4], const uint4* p) {
    uint4 v = __ldg(p);
    r[0] = v.x; r[1] = v.y; r[2] = v.z; r[3] = v.w;
}

// ---------------- kernel 0: init (zero counters + output) ----------------
__global__ void moe_init_kernel(float4* __restrict__ out) {
    int i = blockIdx.x * blockDim.x + threadIdx.x;
    if (i < E_NUM) d_cnt[i] = 0;
    int stride = gridDim.x * blockDim.x;
    for (int j = i; j < T_TOK * H_DIM / 4; j += stride)
        out[j] = make_float4(0.f, 0.f, 0.f, 0.f);
}

// ---------------- kernel 1: router (warp per token) ----------------
__global__ __launch_bounds__(256) void moe_router_kernel(
    const float* __restrict__ x, const float* __restrict__ gw, const float* __restrict__ gb)
{
    int t = blockIdx.x * 8 + (threadIdx.x >> 5);
    int lane = threadIdx.x & 31;
    if (t >= T_TOK) return;
    float s[E_NUM];
    #pragma unroll
    for (int e = 0; e < E_NUM; e++) s[e] = 0.f;
    #pragma unroll 4
    for (int j = 0; j < H_DIM / 32; j++) {
        float xv = x[(size_t)t * H_DIM + j * 32 + lane];
        const float4* g = (const float4*)(gw + (size_t)(j * 32 + lane) * E_NUM);
        float4 g0 = g[0], g1 = g[1];
        s[0] += xv * g0.x; s[1] += xv * g0.y; s[2] += xv * g0.z; s[3] += xv * g0.w;
        s[4] += xv * g1.x; s[5] += xv * g1.y; s[6] += xv * g1.z; s[7] += xv * g1.w;
    }
    #pragma unroll
    for (int e = 0; e < E_NUM; e++) {
        #pragma unroll
        for (int o = 16; o; o >>= 1) s[e] += __shfl_xor_sync(0xffffffffu, s[e], o);
    }
    if (lane == 0) {
        float lg[E_NUM];
        #pragma unroll
        for (int e = 0; e < E_NUM; e++) lg[e] = s[e] + gb[e];
        int i1 = 0; float l1 = lg[0];
        #pragma unroll
        for (int e = 1; e < E_NUM; e++) if (lg[e] > l1) { l1 = lg[e]; i1 = e; }
        int i2 = -1; float l2 = -1e30f;
        #pragma unroll
        for (int e = 0; e < E_NUM; e++) if (e != i1 && lg[e] > l2) { l2 = lg[e]; i2 = e; }
        float p1 = 1.0f / (1.0f + expf(l2 - l1));
        float p2 = 1.0f - p1;
        int q1 = atomicAdd(&d_cnt[i1], 1);
        d_tok[i1 * CAP + q1] = t;  d_wt[i1 * CAP + q1] = p1;
        int q2 = atomicAdd(&d_cnt[i2], 1);
        d_tok[i2 * CAP + q2] = t;  d_wt[i2 * CAP + q2] = p2;
    }
}

// ---------------- kernel 2: gather x rows into A-fragments (zero-padded) ----------------
__global__ __launch_bounds__(128) void moe_xgather_kernel(const float* __restrict__ x) {
    int e  = blockIdx.y;
    int rt = blockIdx.x;
    int M  = d_cnt[e];
    int Mceil = (M + 127) & ~127;
    if (rt * 16 >= Mceil) return;
    int w = threadIdx.x >> 5, lane = threadIdx.x & 31;
    int grp = lane >> 2, t4 = lane & 3;
    int r0 = rt * 16 + grp, r8 = r0 + 8;
    bool v0 = r0 < M, v8 = r8 < M;
    const float* x0 = x + (size_t)(v0 ? d_tok[e * CAP + r0] : 0) * H_DIM;
    const float* x8 = x + (size_t)(v8 ? d_tok[e * CAP + r8] : 0) * H_DIM;
    uint4* dst = d_xg + ((size_t)(e * RT_CAP + rt) * CT1) * 32 + lane;
    for (int ct = w; ct < CT1; ct += 4) {
        int c = ct * 16 + 2 * t4;
        float2 z = make_float2(0.f, 0.f);
        float2 lo0 = v0 ? *(const float2*)(x0 + c)     : z;
        float2 lo8 = v8 ? *(const float2*)(x8 + c)     : z;
        float2 hi0 = v0 ? *(const float2*)(x0 + c + 8) : z;
        float2 hi8 = v8 ? *(const float2*)(x8 + c + 8) : z;
        uint4 o;
        o.x = pk(lo0.x, lo0.y);
        o.y = pk(lo8.x, lo8.y);
        o.z = pk(hi0.x, hi0.y);
        o.w = pk(hi8.x, hi8.y);
        dst[(size_t)ct * 32] = o;
    }
}

// ---------------- kernel 3: pack weights [K][N] f32 -> B-fragments f16 ----------------
// which=0 -> d_w1f, which=1 -> d_w2f  (destination resolved in DEVICE code;
// passing a __device__ symbol from host was the R8 bug)
__global__ __launch_bounds__(256) void moe_wpack_kernel(
    const float* __restrict__ W, int which, int K, int N)
{
    __shared__ float sm[64][68];
    uint4* out = which ? d_w2f : d_w1f;
    int tid = threadIdx.x;
    int k0 = blockIdx.y * 64, n0 = blockIdx.x * 64;
    const float* Wb = W + (size_t)blockIdx.z * K * N;
    #pragma unroll
    for (int it = 0; it < 4; it++) {
        int row = it * 16 + (tid >> 4);
        int col = (tid & 15) * 4;
        float4 v = *(const float4*)(Wb + (size_t)(k0 + row) * N + n0 + col);
        sm[row][col] = v.x; sm[row][col + 1] = v.y;
        sm[row][col + 2] = v.z; sm[row][col + 3] = v.w;
    }
    __syncthreads();
    int w = tid >> 5, lane = tid & 31;
    int grp = lane >> 2, t4 = lane & 3;
    int KT = K >> 4, NT = N >> 4;
    #pragma unroll
    for (int id = w; id < 16; id += 8) {
        int tk = id >> 2, tn = id & 3;
        int kb = tk * 16 + 2 * t4, nl = tn * 16 + grp, nh = nl + 8;
        uint4 o;
        o.x = pk(sm[kb][nl],     sm[kb + 1][nl]);
        o.y = pk(sm[kb + 8][nl], sm[kb + 9][nl]);
        o.z = pk(sm[kb][nh],     sm[kb + 1][nh]);
        o.w = pk(sm[kb + 8][nh], sm[kb + 9][nh]);
        out[(((size_t)blockIdx.z * KT + blockIdx.y * 4 + tk) * NT
             + blockIdx.x * 4 + tn) * 32 + lane] = o;
    }
}

// ================= fragment GEMM mainloop (no smem, no barriers) =================
#define LOADF(AF, BF, ss)                                                    \
    do {                                                                     \
        _Pragma("unroll")                                                    \
        for (int mi = 0; mi < 4; mi++) ldg128(AF[mi], aP[mi] + (size_t)(ss) * 32); \
        _Pragma("unroll")                                                    \
        for (int j = 0; j < 4; j++)                                          \
            ldg128(BF[j], bP + (size_t)(ss) * (BNT) * 32 + j * 32);          \
    } while (0)

#define MMAF(AF, BF)                                                         \
    do {                                                                     \
        _Pragma("unroll")                                                    \
        for (int j = 0; j < 4; j++)                                          \
            _Pragma("unroll")                                                \
            for (int mi = 0; mi < 4; mi++) {                                 \
                mma16816(acc[mi][2 * j],     AF[mi], BF[j][0], BF[j][1]);    \
                mma16816(acc[mi][2 * j + 1], AF[mi], BF[j][2], BF[j][3]);    \
            }                                                                \
    } while (0)

#define GEMM_MAIN(NS_, ABASE, BBASE, BNT_)                                   \
    const int NS = (NS_);                                                    \
    const int BNT = (BNT_);                                                  \
    int tid = threadIdx.x, warp = tid >> 5, lane = tid & 31;                 \
    int wm = warp >> 1, wn = warp & 1;                                       \
    int grp = lane >> 2, t4 = lane & 3;                                      \
    int rt0 = (m0 >> 4) + wm * 4, nt0 = (n0 >> 4) + wn * 4;                  \
    const uint4* aP[4];                                                      \
    _Pragma("unroll")                                                        \
    for (int mi = 0; mi < 4; mi++)                                           \
        aP[mi] = (ABASE) + ((size_t)(rt0 + mi) * NS) * 32 + lane;            \
    const uint4* bP = (BBASE) + (size_t)nt0 * 32 + lane;                     \
    float acc[4][8][4];                                                      \
    _Pragma("unroll")                                                        \
    for (int mi = 0; mi < 4; mi++)                                           \
        _Pragma("unroll")                                                    \
        for (int ni = 0; ni < 8; ni++)                                       \
            _Pragma("unroll")                                                \
            for (int q = 0; q < 4; q++) acc[mi][ni][q] = 0.f;                \
    uint32_t aF0[4][4], bF0[4][4], aF1[4][4], bF1[4][4];                     \
    LOADF(aF0, bF0, 0);                                                      \
    for (int s = 0; s < NS; s += 2) {                                        \
        LOADF(aF1, bF1, s + 1);                                              \
        MMAF(aF0, bF0);                                                      \
        if (s + 2 < NS) LOADF(aF0, bF0, s + 2);                              \
        MMAF(aF1, bF1);                                                      \
    }

// ---------------- kernel 4: GEMM1  h = relu(Xg @ W1[e] + b1) -> h fragments ----------------
__global__ __launch_bounds__(128, 2) void moe_ffn1_kernel(const float* __restrict__ b1)
{
    int e  = blockIdx.z;
    int M  = d_cnt[e];
    int m0 = blockIdx.y * 128;
    if (m0 >= M) return;
    int n0 = blockIdx.x * 128;

    GEMM_MAIN(CT1,
              d_xg  + (size_t)e * RT_CAP * CT1 * 32,
              d_w1f + (size_t)e * CT1 * NT1 * 32,
              NT1)

    // epilogue: relu(acc + b1) packed directly as ffn2 A-fragments
    const float* bb = b1 + (size_t)e * F_DIM + n0 + wn * 64;
    #pragma unroll
    for (int mi = 0; mi < 4; mi++) {
        size_t rbase = ((size_t)(e * RT_CAP) + (rt0 + mi)) * CT2;
        #pragma unroll
        for (int j = 0; j < 4; j++) {
            float2 blo = *(const float2*)(bb + j * 16 + 2 * t4);
            float2 bhi = *(const float2*)(bb + j * 16 + 8 + 2 * t4);
            uint4 o;
            o.x = pk(fmaxf(acc[mi][2*j][0]   + blo.x, 0.f), fmaxf(acc[mi][2*j][1]   + blo.y, 0.f));
            o.y = pk(fmaxf(acc[mi][2*j][2]   + blo.x, 0.f), fmaxf(acc[mi][2*j][3]   + blo.y, 0.f));
            o.z = pk(fmaxf(acc[mi][2*j+1][0] + bhi.x, 0.f), fmaxf(acc[mi][2*j+1][1] + bhi.y, 0.f));
            o.w = pk(fmaxf(acc[mi][2*j+1][2] + bhi.x, 0.f), fmaxf(acc[mi][2*j+1][3] + bhi.y, 0.f));
            d_hf[(rbase + nt0 + j) * 32 + lane] = o;
        }
    }
}

// ---------------- kernel 5: GEMM2  out[tok] += wt*(h @ W2[e] + b2) ----------------
__global__ __launch_bounds__(128, 2) void moe_ffn2_kernel(const float* __restrict__ b2,
                                                          float* __restrict__ out)
{
    int e  = blockIdx.z;
    int M  = d_cnt[e];
    int m0 = blockIdx.y * 128;
    if (m0 >= M) return;
    int n0 = blockIdx.x * 128;

    GEMM_MAIN(CT2,
              d_hf  + (size_t)e * RT_CAP * CT2 * 32,
              d_w2f + (size_t)e * CT2 * NT2 * 32,
              NT2)

    // epilogue: scatter wt*(acc + b2) into out (2 atomic adds per out element total)
    #pragma unroll
    for (int mi = 0; mi < 4; mi++) {
        int r = m0 + wm * 64 + mi * 16 + grp;
        bool v0 = (r < M), v1 = (r + 8 < M);
        int tok0 = 0, tok1 = 0; float wt0 = 0.f, wt1 = 0.f;
        if (v0) { tok0 = d_tok[e * CAP + r];     wt0 = d_wt[e * CAP + r]; }
        if (v1) { tok1 = d_tok[e * CAP + r + 8]; wt1 = d_wt[e * CAP + r + 8]; }
        #pragma unroll
        for (int ni = 0; ni < 8; ni++) {
            int c = n0 + wn * 64 + ni * 8 + t4 * 2;
            float2 bv = *(const float2*)(b2 + (size_t)e * H_DIM + c);
            if (v0) {
                atomicAdd(out + (size_t)tok0 * H_DIM + c,     wt0 * (acc[mi][ni][0] + bv.x));
                atomicAdd(out + (size_t)tok0 * H_DIM + c + 1, wt0 * (acc[mi][ni][1] + bv.y));
            }
            if (v1) {
                atomicAdd(out + (size_t)tok1 * H_DIM + c,     wt1 * (acc[mi][ni][2] + bv.x));
                atomicAdd(out + (size_t)tok1 * H_DIM + c + 1, wt1 * (acc[mi][ni][3] + bv.y));
            }
        }
    }
}

// ---------------- launch ----------------
extern "C" void kernel_launch(void* const* d_in, const int* in_sizes, int n_in,
                              void* d_out, int out_size) {
    const float* x  = (const float*)d_in[0];
    const float* gw = (const float*)d_in[1];
    const float* gb = (const float*)d_in[2];
    const float* w1 = (const float*)d_in[3];
    const float* b1 = (const float*)d_in[4];
    const float* w2 = (const float*)d_in[5];
    const float* b2 = (const float*)d_in[6];
    float* out = (float*)d_out;

    moe_init_kernel<<<128, 256>>>((float4*)d_out);
    moe_router_kernel<<<T_TOK / 8, 256>>>(x, gw, gb);
    moe_xgather_kernel<<<dim3(RT_CAP, E_NUM), 128>>>(x);
    moe_wpack_kernel<<<dim3(F_DIM / 64, H_DIM / 64, E_NUM), 256>>>(w1, 0, H_DIM, F_DIM);
    moe_wpack_kernel<<<dim3(H_DIM / 64, F_DIM / 64, E_NUM), 256>>>(w2, 1, F_DIM, H_DIM);
    moe_ffn1_kernel<<<dim3(F_DIM / 128, CAP / 128, E_NUM), 128>>>(b1);
    moe_ffn2_kernel<<<dim3(H_DIM / 128, CAP / 128, E_NUM), 128>>>(b2, out);
}